// round 2
// baseline (speedup 1.0000x reference)
#include <cuda_runtime.h>
#include <cuda_bf16.h>

// Problem constants: x[B=16, H=256, W=256, C=3, L=8] fp32, scales 1..8.
// Channel dim CHN = C*L = 24 floats = 6 float4 per (b,h,w) position.
#define HW    256
#define CHN   24
#define RT    32          // output rows per row-strip
#define CHUNK 64          // output cols per col-chunk
#define HALO  7
#define NFMAX 426         // (CHUNK+HALO) * CHN / 4
#define NOUT  384         // CHUNK * CHN / 4
#define BLK   384
#define NSMEM (19 * NFMAX)            // float4 units
#define SMEMBYTES (NSMEM * 16)        // 129504 B dynamic smem

__device__ __forceinline__ float4 fmax4(float4 a, float4 b) {
    return make_float4(fmaxf(a.x, b.x), fmaxf(a.y, b.y),
                       fmaxf(a.z, b.z), fmaxf(a.w, b.w));
}
__device__ __forceinline__ void fadd4(float4& a, float4 b) {
    a.x += b.x; a.y += b.y; a.z += b.z; a.w += b.w;
}

// Main streaming kernel: one CTA = (batch, row-strip, col-chunk).
// Ring buffers in smem hold vertical doubling planes; each iteration loads one
// input row, updates p2/p4 rings, emits v3/v5/v6/v7/v8 temp planes, then each
// thread computes horizontal window maxes for its (col, ch4) item and
// accumulates per-scale sums in registers.
__global__ __launch_bounds__(BLK)
void sgb_main(const float* __restrict__ x, float* __restrict__ out) {
    extern __shared__ float4 sm[];
    float4* xr = sm;                 // 2 rows  (x ring)
    float4* p2 = sm + 2 * NFMAX;     // 7 rows  (vertical max of 2 rows)
    float4* p4 = sm + 9 * NFMAX;     // 5 rows  (vertical max of 4 rows)
    float4* tv = sm + 14 * NFMAX;    // 5 rows  (v3, v5, v6, v7, v8)

    const int t = threadIdx.x;
    const int b = blockIdx.z, strip = blockIdx.y, chunk = blockIdx.x;
    const int r0 = strip * RT;
    const int c0 = chunk * CHUNK;
    const int ncols = min(CHUNK + HALO, HW - c0);
    const int NF = ncols * 6;        // float4 items per smem row

    float4 acc[8];
#pragma unroll
    for (int s = 0; s < 8; ++s) acc[s] = make_float4(0.f, 0.f, 0.f, 0.f);

    const float4* xbase = (const float4*)x;

    for (int r = r0; r <= r0 + RT + 6; ++r) {
        // ---- load row r + ring updates (pointwise; fixed item->thread map,
        //      so no sync needed inside this block) ----
        if (r < HW) {
            const float4* grow = xbase + (size_t)((b * HW + r) * HW + c0) * 6;
            const bool ownrow = (r < r0 + RT);
#pragma unroll 2
            for (int f = t; f < NF; f += BLK) {
                float4 xv = grow[f];
                xr[(r & 1) * NFMAX + f] = xv;
                if (ownrow && f < NOUT) fadd4(acc[0], xv);   // scale 1
                if (r > r0) {
                    float4 xp  = xr[((r - 1) & 1) * NFMAX + f];
                    float4 p2v = fmax4(xv, xp);              // p2[r-1]
                    p2[((r - 1) % 7) * NFMAX + f] = p2v;
                    if (r >= r0 + 3) {
                        float4 p2b = p2[((r - 3) % 7) * NFMAX + f];
                        float4 p4v = fmax4(p2v, p2b);        // p4[r-3]
                        p4[((r - 3) % 5) * NFMAX + f] = p4v;
                    }
                }
            }
        }

        const int i = r - 7;   // output row being finalized this iteration
        if (i >= r0) {
            // ---- phase A: build odd vertical planes into temps ----
#pragma unroll 2
            for (int f = t; f < NF; f += BLK) {
                float4 p2i  = p2[(i % 7) * NFMAX + f];
                float4 p2i1 = p2[((i + 1) % 7) * NFMAX + f];
                float4 p4i  = p4[(i % 5) * NFMAX + f];
                float4 p4i1 = p4[((i + 1) % 5) * NFMAX + f];
                float4 p4i2 = p4[((i + 2) % 5) * NFMAX + f];
                float4 p4i3 = p4[((i + 3) % 5) * NFMAX + f];
                float4 p4i4 = p4[((i + 4) % 5) * NFMAX + f];
                tv[0 * NFMAX + f] = fmax4(p2i, p2i1);   // v3 (rows i..i+2)
                tv[1 * NFMAX + f] = fmax4(p4i, p4i1);   // v5 (i..i+4)
                tv[2 * NFMAX + f] = fmax4(p4i, p4i2);   // v6 (i..i+5)
                tv[3 * NFMAX + f] = fmax4(p4i, p4i3);   // v7 (i..i+6)
                tv[4 * NFMAX + f] = fmax4(p4i, p4i4);   // v8 (i..i+7)
            }
            __syncthreads();

            // ---- phase B: horizontal window max + accumulate ----
            {
                const int w  = t / 6;        // local output col
                const int wg = c0 + w;       // global output col
                const float4* pl[7] = {
                    p2 + (i % 7) * NFMAX,    // s=2
                    tv + 0 * NFMAX,          // s=3
                    p4 + (i % 5) * NFMAX,    // s=4
                    tv + 1 * NFMAX,          // s=5
                    tv + 2 * NFMAX,          // s=6
                    tv + 3 * NFMAX,          // s=7
                    tv + 4 * NFMAX           // s=8
                };
#pragma unroll
                for (int s = 2; s <= 8; ++s) {
                    if (i + s <= HW && wg + s <= HW) {
                        const float4* p = pl[s - 2];
                        float4 win = p[t];
#pragma unroll
                        for (int k = 1; k < s; ++k)
                            win = fmax4(win, p[t + 6 * k]);
                        fadd4(acc[s - 1], win);
                    }
                }
            }
            __syncthreads();   // protect rings/temps before next iteration writes
        }
    }

    // ---- block reduction over the 64 columns sharing each (ch4, scale) ----
    __syncthreads();
    float4* red = sm;          // 6*8*64 = 3072 float4, reuses ring space
    {
        const int w = t / 6, ch4 = t % 6;
#pragma unroll
        for (int s = 0; s < 8; ++s) red[(ch4 * 8 + s) * 64 + w] = acc[s];
    }
    __syncthreads();
    if (t < 48) {
        const int ch4 = t / 8, s = t % 8;
        float4 sum = make_float4(0.f, 0.f, 0.f, 0.f);
        const float4* row = red + (ch4 * 8 + s) * 64;
        for (int w = 0; w < 64; ++w) fadd4(sum, row[w]);
        const int ch = ch4 * 4;
        float* o = out + (size_t)(b * CHN) * 8 + s;
        atomicAdd(o + (ch + 0) * 8, sum.x);
        atomicAdd(o + (ch + 1) * 8, sum.y);
        atomicAdd(o + (ch + 2) * 8, sum.z);
        atomicAdd(o + (ch + 3) * 8, sum.w);
    }
}

__global__ void sgb_zero(float* __restrict__ out) {
    int i = blockIdx.x * blockDim.x + threadIdx.x;
    if (i < 16 * CHN * 8) out[i] = 0.f;
}

__global__ void sgb_finalize(float* __restrict__ out) {
    int i = blockIdx.x * blockDim.x + threadIdx.x;
    if (i < 16 * CHN * 8) out[i] = fmaxf(out[i], 0.f) + 1.f;
}

extern "C" void kernel_launch(void* const* d_in, const int* in_sizes, int n_in,
                              void* d_out, int out_size) {
    (void)in_sizes; (void)n_in; (void)out_size;
    const float* x = (const float*)d_in[0];   // x[16,256,256,3,8] fp32
    float* out = (float*)d_out;               // [16,3,8,8] fp32

    cudaFuncSetAttribute(sgb_main,
                         cudaFuncAttributeMaxDynamicSharedMemorySize,
                         SMEMBYTES);

    sgb_zero<<<12, 256>>>(out);
    dim3 grid(HW / CHUNK, HW / RT, 16);       // (4 chunks, 8 strips, 16 batch)
    sgb_main<<<grid, BLK, SMEMBYTES>>>(x, out);
    sgb_finalize<<<12, 256>>>(out);
}

// round 3
// speedup vs baseline: 1.7484x; 1.7484x over previous
#include <cuda_runtime.h>
#include <cuda_bf16.h>

// x[B=16, H=256, W=256, C=3, L=8] fp32 -> out[16,3,8,8]
// CHN = C*L = 24 floats = 6 float4 per (b,h,w).
#define HW    256
#define CHN   24
#define CHUNK 64          // output cols per CTA
#define RT    64          // output rows per CTA
#define BLK   384
#define ST    427         // padded plane-row stride in float4 (427*4 % 32 == 12 -> conflict-free)
#define P2R   16          // p2 ring rows
#define P4R   16          // p4 ring rows
#define SMEM_F4  ((P2R + P4R) * ST)
#define SMEMBYTES (SMEM_F4 * 16)       // 218624 B

__device__ __forceinline__ float4 fmax4(float4 a, float4 b) {
    return make_float4(fmaxf(a.x, b.x), fmaxf(a.y, b.y),
                       fmaxf(a.z, b.z), fmaxf(a.w, b.w));
}
__device__ __forceinline__ void fadd4(float4& a, float4 b) {
    a.x += b.x; a.y += b.y; a.z += b.z; a.w += b.w;
}

// One CTA = (batch, 64-row strip, 64-col chunk + 7 col halo).
// Load phase (per batch of 4 output rows): stream input rows, build p2 (2-row
// vertical max) and p4 (4-row vertical max) ring rows in smem; x-prev and the
// 2-step p2 history live in registers (fixed item->thread map), so smem cost
// is 2 STS per element. One __syncthreads per batch (ring slot liveness allows
// the load of batch k+1 to overlap stragglers of phase B of batch k).
// Phase B: thread = (ri row-in-batch, ch4, g col-group of 4); builds the 7
// vertical planes in registers from p2/p4 rows and computes all horizontal
// window maxes for its 4 columns with shared m2/m4 doubling.
__global__ __launch_bounds__(BLK, 1)
void sgb_main(const float* __restrict__ x, float* __restrict__ out) {
    extern __shared__ float4 sm[];
    float4* P2 = sm;
    float4* P4 = sm + P2R * ST;

    const int t  = threadIdx.x;
    const int b  = blockIdx.z;
    const int r0 = blockIdx.y * RT;
    const int c0 = blockIdx.x * CHUNK;
    const int ncols = min(CHUNK + 7, HW - c0);
    const int NF = ncols * 6;                 // float4 items per plane row

    // ---- load-phase per-item register state ----
    const bool has2 = (t + BLK < NF);         // threads 0..41 own a 2nd item
    float4 xprev0 = {0,0,0,0}, p2m1_0 = {0,0,0,0}, p2m2_0 = {0,0,0,0};
    float4 xprev1 = {0,0,0,0}, p2m1_1 = {0,0,0,0}, p2m2_1 = {0,0,0,0};

    // ---- phase-B mapping: t = ((g*6 + ch4)*4 + ri) ----
    const int ri  = t & 3;
    const int gch = t >> 2;
    const int ch4 = gch % 6;
    const int g   = gch / 6;                  // 0..15 col group (4 cols each)
    const int baseitem = g * 24 + ch4;
    const int collim = HW - (c0 + g * 4);     // col j valid for scale s iff j + s <= collim

    float4 acc[8];
#pragma unroll
    for (int s = 0; s < 8; ++s) acc[s] = make_float4(0.f, 0.f, 0.f, 0.f);

    const float4* X = (const float4*)x;
    int loaded = r0;

    for (int i = r0; i < r0 + RT; i += 4) {
        // ---- load phase: ensure input rows through i+10 are processed ----
        const int rowend = min(i + 10, HW - 1);
        for (; loaded <= rowend; ++loaded) {
            const int rr = loaded;
            const float4* grow = X + ((size_t)(b * HW + rr) * HW + c0) * 6;
            {   // item 0 (always valid: t < 384 <= NF)
                float4 xv = grow[t];
                if (rr < r0 + RT) fadd4(acc[0], xv);          // scale 1 (cols 0..63 only)
                if (rr > r0) {
                    float4 p2v = fmax4(xv, xprev0);
                    P2[((rr - 1) & (P2R - 1)) * ST + t] = p2v;
                    if (rr >= r0 + 3)
                        P4[((rr - 3) & (P4R - 1)) * ST + t] = fmax4(p2v, p2m2_0);
                    p2m2_0 = p2m1_0; p2m1_0 = p2v;
                }
                xprev0 = xv;
            }
            if (has2) {  // item 1 is a halo column (col >= 64): no scale-1 add
                const int f = t + BLK;
                float4 xv = grow[f];
                if (rr > r0) {
                    float4 p2v = fmax4(xv, xprev1);
                    P2[((rr - 1) & (P2R - 1)) * ST + f] = p2v;
                    if (rr >= r0 + 3)
                        P4[((rr - 3) & (P4R - 1)) * ST + f] = fmax4(p2v, p2m2_1);
                    p2m2_1 = p2m1_1; p2m1_1 = p2v;
                }
                xprev1 = xv;
            }
        }
        __syncthreads();

        // ---- phase B: outputs o = i + ri ----
        const int o = i + ri;
        const int rlim = HW - o;              // scale s valid iff s <= rlim
        const float4* p2o  = P2 + ((o    ) & (P2R - 1)) * ST + baseitem;
        const float4* p2o1 = P2 + ((o + 1) & (P2R - 1)) * ST + baseitem;
        const float4* p4o  = P4 + ((o    ) & (P4R - 1)) * ST + baseitem;
        const float4* p4o1 = P4 + ((o + 1) & (P4R - 1)) * ST + baseitem;
        const float4* p4o2 = P4 + ((o + 2) & (P4R - 1)) * ST + baseitem;
        const float4* p4o3 = P4 + ((o + 3) & (P4R - 1)) * ST + baseitem;
        const float4* p4o4 = P4 + ((o + 4) & (P4R - 1)) * ST + baseitem;

        // scales 2,3 from p2
        {
            float4 a[6];
#pragma unroll
            for (int k = 0; k < 6; ++k) a[k] = p2o[6 * k];
            if (rlim >= 2) {
                float4 s = make_float4(0.f, 0.f, 0.f, 0.f);
#pragma unroll
                for (int j = 0; j < 4; ++j)
                    if (j + 2 <= collim) fadd4(s, fmax4(a[j], a[j + 1]));
                fadd4(acc[1], s);
            }
            if (rlim >= 3) {
                float4 bb[6];
#pragma unroll
                for (int k = 0; k < 6; ++k) bb[k] = fmax4(a[k], p2o1[6 * k]);
                float4 s = make_float4(0.f, 0.f, 0.f, 0.f);
#pragma unroll
                for (int j = 0; j < 4; ++j)
                    if (j + 3 <= collim)
                        fadd4(s, fmax4(fmax4(bb[j], bb[j + 1]), bb[j + 2]));
                fadd4(acc[2], s);
            }
        }
        // scales 4..8 from p4 (a4 = p4[o] shared across all of them)
        {
            float4 a4[11];
#pragma unroll
            for (int k = 0; k < 11; ++k) a4[k] = p4o[6 * k];
            if (rlim >= 4) {
                float4 m2[6];
#pragma unroll
                for (int k = 0; k < 6; ++k) m2[k] = fmax4(a4[k], a4[k + 1]);
                float4 s = make_float4(0.f, 0.f, 0.f, 0.f);
#pragma unroll
                for (int j = 0; j < 4; ++j)
                    if (j + 4 <= collim) fadd4(s, fmax4(m2[j], m2[j + 2]));
                fadd4(acc[3], s);
            }
            if (rlim >= 5) {
                float4 bb[8];
#pragma unroll
                for (int k = 0; k < 8; ++k) bb[k] = fmax4(a4[k], p4o1[6 * k]);
                float4 m2[6];
#pragma unroll
                for (int k = 0; k < 6; ++k) m2[k] = fmax4(bb[k], bb[k + 1]);
                float4 s = make_float4(0.f, 0.f, 0.f, 0.f);
#pragma unroll
                for (int j = 0; j < 4; ++j)
                    if (j + 5 <= collim)
                        fadd4(s, fmax4(fmax4(m2[j], m2[j + 2]), bb[j + 4]));
                fadd4(acc[4], s);
            }
            if (rlim >= 6) {
                float4 bb[9];
#pragma unroll
                for (int k = 0; k < 9; ++k) bb[k] = fmax4(a4[k], p4o2[6 * k]);
                float4 m2[8];
#pragma unroll
                for (int k = 0; k < 8; ++k) m2[k] = fmax4(bb[k], bb[k + 1]);
                float4 s = make_float4(0.f, 0.f, 0.f, 0.f);
#pragma unroll
                for (int j = 0; j < 4; ++j)
                    if (j + 6 <= collim)
                        fadd4(s, fmax4(fmax4(m2[j], m2[j + 2]), m2[j + 4]));
                fadd4(acc[5], s);
            }
            if (rlim >= 7) {
                float4 bb[10];
#pragma unroll
                for (int k = 0; k < 10; ++k) bb[k] = fmax4(a4[k], p4o3[6 * k]);
                float4 m2[9];
#pragma unroll
                for (int k = 0; k < 9; ++k) m2[k] = fmax4(bb[k], bb[k + 1]);
                float4 m4[7];
#pragma unroll
                for (int j = 0; j < 7; ++j) m4[j] = fmax4(m2[j], m2[j + 2]);
                float4 s = make_float4(0.f, 0.f, 0.f, 0.f);
#pragma unroll
                for (int j = 0; j < 4; ++j)
                    if (j + 7 <= collim) fadd4(s, fmax4(m4[j], m4[j + 3]));
                fadd4(acc[6], s);
            }
            if (rlim >= 8) {
                float4 bb[11];
#pragma unroll
                for (int k = 0; k < 11; ++k) bb[k] = fmax4(a4[k], p4o4[6 * k]);
                float4 m2[10];
#pragma unroll
                for (int k = 0; k < 10; ++k) m2[k] = fmax4(bb[k], bb[k + 1]);
                float4 m4[8];
#pragma unroll
                for (int j = 0; j < 8; ++j) m4[j] = fmax4(m2[j], m2[j + 2]);
                float4 s = make_float4(0.f, 0.f, 0.f, 0.f);
#pragma unroll
                for (int j = 0; j < 4; ++j)
                    if (j + 8 <= collim) fadd4(s, fmax4(m4[j], m4[j + 4]));
                fadd4(acc[7], s);
            }
        }
        // no trailing sync: next batch's ring writes touch disjoint slots;
        // the single sync after its load phase restores full ordering.
    }

    // ---- block reduction: sum over the 64 (col/ri) owners per (ch4, scale) ----
    __syncthreads();
    float4* red = sm;                         // 48*64 = 3072 float4, reuses rings
    red[((t % 6) * 8 + 0) * 64 + (t / 6)] = acc[0];   // scale 1: load-phase mapping
#pragma unroll
    for (int si = 1; si < 8; ++si)
        red[(ch4 * 8 + si) * 64 + (g * 4 + ri)] = acc[si];
    __syncthreads();
    if (t < 48) {
        const int c4 = t / 8, si = t % 8;
        float4 s = make_float4(0.f, 0.f, 0.f, 0.f);
        const float4* row = red + (c4 * 8 + si) * 64;
#pragma unroll 8
        for (int w = 0; w < 64; ++w) fadd4(s, row[w]);
        float* op = out + (size_t)b * (CHN * 8) + si;
        atomicAdd(op + (c4 * 4 + 0) * 8, s.x);
        atomicAdd(op + (c4 * 4 + 1) * 8, s.y);
        atomicAdd(op + (c4 * 4 + 2) * 8, s.z);
        atomicAdd(op + (c4 * 4 + 3) * 8, s.w);
    }
}

__global__ void sgb_zero(float* __restrict__ out) {
    int i = blockIdx.x * blockDim.x + threadIdx.x;
    if (i < 16 * CHN * 8) out[i] = 0.f;
}

__global__ void sgb_finalize(float* __restrict__ out) {
    int i = blockIdx.x * blockDim.x + threadIdx.x;
    if (i < 16 * CHN * 8) out[i] = fmaxf(out[i], 0.f) + 1.f;
}

extern "C" void kernel_launch(void* const* d_in, const int* in_sizes, int n_in,
                              void* d_out, int out_size) {
    (void)in_sizes; (void)n_in; (void)out_size;
    const float* x = (const float*)d_in[0];   // x[16,256,256,3,8] fp32
    float* out = (float*)d_out;               // [16,3,8,8] fp32

    cudaFuncSetAttribute(sgb_main,
                         cudaFuncAttributeMaxDynamicSharedMemorySize,
                         SMEMBYTES);

    sgb_zero<<<12, 256>>>(out);
    dim3 grid(HW / CHUNK, HW / RT, 16);       // (4 chunks, 4 strips, 16 batch) = 256 CTAs
    sgb_main<<<grid, BLK, SMEMBYTES>>>(x, out);
    sgb_finalize<<<12, 256>>>(out);
}